// round 8
// baseline (speedup 1.0000x reference)
#include <cuda_runtime.h>
#include <cuda_bf16.h>

#define NBINS 256
#define NIMG  96
#define BATCH 32            // 3 batches
#define HDIM  512
#define WDIM  512
#define CHUNK 16
#define PI_F  3.14159265358979323846f

#define TILES_PER_IMG (128 * 128)
#define BUF_FLOATS (4 * BATCH * TILES_PER_IMG * 4)   // 33.5 MB

// zero-initialized at load; merge restores it to exactly zero every call
// (block-exclusive coalesced zero-stores) -> graph-replay safe.
__device__ float    g_buf[BUF_FLOATS];
__device__ unsigned g_vmax_u[NIMG];

__device__ __forceinline__ void red4(float* a, float x, float y, float z, float w) {
    asm volatile("red.global.add.v4.f32 [%0], {%1,%2,%3,%4};"
                 :: "l"(a), "f"(x), "f"(y), "f"(z), "f"(w) : "memory");
}

// ---------------------------------------------------------------------------
// Kernel 1: soft co-occurrence scatter, ONE v4 red per pixel pair.
// Parity copy c = (ia&1)*2 + (ib&1); tile (tr,tc) = ((ia+1)>>1, (ib+1)>>1).
// Lane order: {wa0*wb0, wa0*wb1, wa1*wb0, wa1*wb1} = rows{ia,ia+1}xcols{ib,ib+1}.
// grid = (2, 32, BATCH), block = 256
// ---------------------------------------------------------------------------
__global__ void __launch_bounds__(256) k_hist(const float* __restrict__ X,
                                              int img0, int zero_vmax) {
    if (zero_vmax && blockIdx.x == 0 && blockIdx.y == 0 && blockIdx.z == 0 &&
        threadIdx.x < NIMG)
        g_vmax_u[threadIdx.x] = 0u;

    const int img_l = blockIdx.z;
    const int col   = blockIdx.x * blockDim.x + threadIdx.x;
    const int r0    = blockIdx.y * CHUNK;

    const float* __restrict__ base =
        X + (size_t)(img0 + img_l) * (HDIM * WDIM) + col;

    float a  = __ldg(base + (size_t)r0 * WDIM);
    float fa = fminf(floorf(a), 254.0f);
    int   ia = (int)fa;
    float wa0 = 0.5f * (1.0f + __cosf(PI_F * (a - fa)));

    const int rmax = min(r0 + CHUNK, HDIM - 1);
    for (int r = r0; r < rmax; ++r) {
        float b  = __ldg(base + (size_t)(r + 1) * WDIM);
        float fb = fminf(floorf(b), 254.0f);
        int   ib = (int)fb;
        float wb0 = 0.5f * (1.0f + __cosf(PI_F * (b - fb)));

        const float wa1 = 1.0f - wa0;
        const float wb1 = 1.0f - wb0;

        const int c  = ((ia & 1) << 1) | (ib & 1);
        const int tr = (ia + 1) >> 1;
        const int tc = (ib + 1) >> 1;
        float* p = g_buf + ((((c * BATCH + img_l) << 14) + (tr << 7) + tc) << 2);
        red4(p, wa0 * wb0, wa0 * wb1, wa1 * wb0, wa1 * wb1);

        a = b; ia = ib; wa0 = wb0;
    }
}

// ---------------------------------------------------------------------------
// Kernel 2: merge + self-zero + per-image max. 256 threads, 2 bins/thread.
// Block bx -> output rows i = 2bx, 2bx+1. Thread t: di = t>>7 (row),
// j' = t&127 (column pair); bins (i, 2j') and (i, 2j'+1).
// Per row-parity pr: float2 from copy pr*2 tile (tr,j') lanes (ra*2, ra*2+1)
// feeds BOTH bins; two scalars from copy pr*2+1.
// Zero ownership (per img, exclusive to block bx):
//   copies 0,1: full float4 tile-row bx
//   copies 2,3: hi half (lanes 2,3) of row bx, lo half (lanes 0,1) of row bx+1
// grid = (128, BATCH), block = 256
// ---------------------------------------------------------------------------
__global__ void __launch_bounds__(256) k_merge(float* __restrict__ out,
                                               int img0) {
    const int img_l = blockIdx.y;
    const int bx    = blockIdx.x;
    const int t     = threadIdx.x;
    const int di    = t >> 7;
    const int jp    = t & 127;            // column pair j' -> bins 2j', 2j'+1
    const int i     = (bx << 1) + di;

    const float2* __restrict__ buf2 = reinterpret_cast<const float2*>(g_buf);

    float s0 = 0.0f, s1 = 0.0f;
    #pragma unroll
    for (int pr = 0; pr < 2; ++pr) {
        const int tr = (i + pr) >> 1;
        const int ra = (i + pr) & 1;
        if (tr < 128) {
            const int c0 = pr << 1;       // col-parity 0 copy
            const int c1 = c0 | 1;        // col-parity 1 copy
            // float2 at copy c0, tile (tr, jp), lane pair (ra*2, ra*2+1)
            float2 v = buf2[(((((c0 * BATCH + img_l) << 14) + (tr << 7) + jp) << 1) + ra)];
            s0 += v.x;
            s1 += v.y;
            // scalar: copy c1, tile (tr, jp), lane ra*2+1 -> bin 2j'
            const int base1 = (((c1 * BATCH + img_l) << 14) + (tr << 7)) << 2;
            s0 += g_buf[base1 + (jp << 2) + (ra << 1) + 1];
            // scalar: copy c1, tile (tr, jp+1), lane ra*2 -> bin 2j'+1
            if (jp < 127)
                s1 += g_buf[base1 + ((jp + 1) << 2) + (ra << 1)];
        }
    }
    reinterpret_cast<float2*>(out + ((size_t)(img0 + img_l) << 16) + (i << 8))[jp] =
        make_float2(s0, s1);

    __syncthreads();   // all block reads done before zeroing owned region

    // A) copies 0,1: full float4 tile-row bx (256 float4 stores, 1/thread)
    {
        const int pc = t >> 7;
        const int tc = t & 127;
        reinterpret_cast<float4*>(g_buf)[((pc * BATCH + img_l) << 14) + (bx << 7) + tc] =
            make_float4(0.f, 0.f, 0.f, 0.f);
    }
    // B) copies 2,3: two float2 stores per thread
    {
        const int c  = 2 + (t >> 7);
        const int tc = t & 127;
        const int rowbase = ((((c * BATCH + img_l) << 14) + (bx << 7) + tc) << 1);
        float2* b2 = reinterpret_cast<float2*>(g_buf);
        b2[rowbase + 1] = make_float2(0.f, 0.f);             // row bx, hi half
        if (bx < 127)
            b2[rowbase + (128 << 1)] = make_float2(0.f, 0.f); // row bx+1, lo half
    }

    // per-image max (values >= 0: uint bits monotonic)
    float m = fmaxf(s0, s1);
    #pragma unroll
    for (int o = 16; o > 0; o >>= 1)
        m = fmaxf(m, __shfl_xor_sync(0xFFFFFFFFu, m, o));
    __shared__ float sm[8];
    if ((t & 31) == 0) sm[t >> 5] = m;
    __syncthreads();
    if (t < 8) {
        m = sm[t];
        #pragma unroll
        for (int o = 4; o > 0; o >>= 1)
            m = fmaxf(m, __shfl_xor_sync(0xFFu, m, o));
        if (t == 0)
            atomicMax(&g_vmax_u[img0 + img_l], __float_as_uint(m));
    }
}

// ---------------------------------------------------------------------------
// Kernel 3: scale each histogram by 1/vmax.  grid = (64, NIMG)
// ---------------------------------------------------------------------------
__global__ void __launch_bounds__(256) k_norm(float* __restrict__ out) {
    const int img = blockIdx.y;
    const float inv = 1.0f / __uint_as_float(g_vmax_u[img]);
    float4* __restrict__ h4 = reinterpret_cast<float4*>(out + ((size_t)img << 16));
    const int i = blockIdx.x * blockDim.x + threadIdx.x;   // [0, 16384)
    float4 v = h4[i];
    v.x *= inv; v.y *= inv; v.z *= inv; v.w *= inv;
    h4[i] = v;
}

// ---------------------------------------------------------------------------
extern "C" void kernel_launch(void* const* d_in, const int* in_sizes, int n_in,
                              void* d_out, int out_size) {
    const float* X = (const float*)d_in[0];
    float* out = (float*)d_out;

    const dim3 hgrid(WDIM / 256, (HDIM - 1 + CHUNK - 1) / CHUNK, BATCH);
    const dim3 mgrid(128, BATCH);

    for (int b = 0; b < NIMG / BATCH; ++b) {
        k_hist <<<hgrid, 256>>>(X, b * BATCH, b == 0);
        k_merge<<<mgrid, 256>>>(out, b * BATCH);
    }

    dim3 ngrid((NBINS * NBINS / 4) / 256, NIMG);
    k_norm<<<ngrid, 256>>>(out);
}